// round 17
// baseline (speedup 1.0000x reference)
#include <cuda_runtime.h>
#include <cuda_fp16.h>
#include <cuda_bf16.h>
#include <math_constants.h>

// ---------------------------------------------------------------------------
// SwinV2 block: window cosine-attention + res-post-norm MLP
// b=2, H=W=192, C=128, WS=16, NH=8, d=16
// GEMMs: R15 BK=32 reg-prefetch. Attention: quad query-blocked, fp32 exp2 on
// shifted logits, softmax denominator via ones-MMA.
// ---------------------------------------------------------------------------

#define M_TOK   73728
#define C_DIM   128
#define NH      8
#define HD      16
#define NWIN    288
#define NTOK    256
#define IMG     192
#define WPR     12
#define LOG2E   1.4426950408889634f

typedef unsigned int u32;

__device__ __half g_qkvh [ (size_t)M_TOK * 384 ];
__device__ float4 g_biasF[ (size_t)NH * 16 * 32 * 32 ];   // fp32 shifted bias
__device__ __half g_attnh[ (size_t)M_TOK * C_DIM ];
__device__ float  g_x1   [ (size_t)M_TOK * C_DIM ];
__device__ __half g_hidh [ (size_t)M_TOK * 256 ];

#define MMA16816(d0,d1,d2,d3,a0,a1,a2,a3,b0,b1)                          \
    asm volatile(                                                        \
        "mma.sync.aligned.m16n8k16.row.col.f32.f16.f16.f32 "             \
        "{%0,%1,%2,%3}, {%4,%5,%6,%7}, {%8,%9}, {%0,%1,%2,%3};"          \
        : "+f"(d0), "+f"(d1), "+f"(d2), "+f"(d3)                         \
        : "r"(a0), "r"(a1), "r"(a2), "r"(a3), "r"(b0), "r"(b1))

__device__ __forceinline__ float ex2f(float x)
{
    float r;
    asm("ex2.approx.f32 %0, %1;" : "=f"(r) : "f"(x));
    return r;
}

// ---------------------------------------------------------------------------
// fp16 tensor-core GEMM (R15 structure: BK=32, register prefetch).
// act: 0 none, 1 exact GELU, 2 fused res + LayerNorm (N==128, C fp32).
// ---------------------------------------------------------------------------
template<bool A_HALF, bool C_HALF, int ACT>
__global__ __launch_bounds__(256) void hgemm_kernel(
    const void* __restrict__ Av, const float* __restrict__ B,
    const float* __restrict__ bias, void* __restrict__ Cv,
    int M, int N, int K,
    const float* __restrict__ res,
    const float* __restrict__ lnw, const float* __restrict__ lnb)
{
    __shared__ __half As[128][40];
    __shared__ __half Bs[32][136];
    __shared__ float2 red[128][4];

    const float*  Af = (const float*)Av;
    const __half* Ah = (const __half*)Av;
    float*  Cf = (float*)Cv;
    __half* Ch = (__half*)Cv;

    const int tid  = threadIdx.x;
    const int lane = tid & 31;
    const int wid  = tid >> 5;
    const int warp_m = wid >> 2;
    const int warp_n = wid & 3;
    const int brow = blockIdx.y * 128;
    const int bcol = blockIdx.x * 128;

    const int a_m0 = tid >> 3;
    const int a_k4 = (tid & 7) << 2;
    const int a_m0h = tid >> 2;
    const int a_k8  = (tid & 3) << 3;
    const int b_k0 = tid >> 5;
    const int b_n4 = (tid & 31) << 2;

    const u32 a_smem = (u32)__cvta_generic_to_shared(&As[0][0]);
    const u32 b_smem = (u32)__cvta_generic_to_shared(&Bs[0][0]);

    float acc[4][4][4];
    #pragma unroll
    for (int mi = 0; mi < 4; mi++)
        #pragma unroll
        for (int ni = 0; ni < 4; ni++)
            #pragma unroll
            for (int z = 0; z < 4; z++) acc[mi][ni][z] = 0.f;

    float4 a_pf[4];
    uint4  a_pfh[2];
    float4 b_pf[4];
    if (A_HALF) {
        #pragma unroll
        for (int t = 0; t < 2; t++)
            a_pfh[t] = *reinterpret_cast<const uint4*>(
                &Ah[(size_t)(brow + a_m0h + t * 64) * K + a_k8]);
    } else {
        #pragma unroll
        for (int t = 0; t < 4; t++)
            a_pf[t] = *reinterpret_cast<const float4*>(
                &Af[(size_t)(brow + a_m0 + t * 32) * K + a_k4]);
    }
    #pragma unroll
    for (int t = 0; t < 4; t++)
        b_pf[t] = *reinterpret_cast<const float4*>(
            &B[(size_t)(b_k0 + t * 8) * N + bcol + b_n4]);

    for (int kt = 0; kt < K; kt += 32) {
        if (A_HALF) {
            #pragma unroll
            for (int t = 0; t < 2; t++)
                *reinterpret_cast<uint4*>(&As[a_m0h + t * 64][a_k8]) = a_pfh[t];
        } else {
            #pragma unroll
            for (int t = 0; t < 4; t++) {
                __half2 h0 = __float22half2_rn(make_float2(a_pf[t].x, a_pf[t].y));
                __half2 h1 = __float22half2_rn(make_float2(a_pf[t].z, a_pf[t].w));
                *reinterpret_cast<__half2*>(&As[a_m0 + t * 32][a_k4 + 0]) = h0;
                *reinterpret_cast<__half2*>(&As[a_m0 + t * 32][a_k4 + 2]) = h1;
            }
        }
        #pragma unroll
        for (int t = 0; t < 4; t++) {
            __half2 g0 = __float22half2_rn(make_float2(b_pf[t].x, b_pf[t].y));
            __half2 g1 = __float22half2_rn(make_float2(b_pf[t].z, b_pf[t].w));
            *reinterpret_cast<__half2*>(&Bs[b_k0 + t * 8][b_n4 + 0]) = g0;
            *reinterpret_cast<__half2*>(&Bs[b_k0 + t * 8][b_n4 + 2]) = g1;
        }
        __syncthreads();

        if (kt + 32 < K) {
            if (A_HALF) {
                #pragma unroll
                for (int t = 0; t < 2; t++)
                    a_pfh[t] = *reinterpret_cast<const uint4*>(
                        &Ah[(size_t)(brow + a_m0h + t * 64) * K + kt + 32 + a_k8]);
            } else {
                #pragma unroll
                for (int t = 0; t < 4; t++)
                    a_pf[t] = *reinterpret_cast<const float4*>(
                        &Af[(size_t)(brow + a_m0 + t * 32) * K + kt + 32 + a_k4]);
            }
            #pragma unroll
            for (int t = 0; t < 4; t++)
                b_pf[t] = *reinterpret_cast<const float4*>(
                    &B[(size_t)(kt + 32 + b_k0 + t * 8) * N + bcol + b_n4]);
        }

        #pragma unroll
        for (int ks = 0; ks < 32; ks += 16) {
            u32 af[4][4];
            #pragma unroll
            for (int mi = 0; mi < 4; mi++) {
                int r = warp_m * 64 + mi * 16 + (lane & 15);
                int c = ks + ((lane >> 4) << 3);
                u32 addr = a_smem + (u32)(r * 40 + c) * 2u;
                asm volatile(
                    "ldmatrix.sync.aligned.m8n8.x4.shared.b16 {%0,%1,%2,%3}, [%4];"
                    : "=r"(af[mi][0]), "=r"(af[mi][1]), "=r"(af[mi][2]), "=r"(af[mi][3])
                    : "r"(addr));
            }
            u32 bf[4][2];
            #pragma unroll
            for (int p = 0; p < 2; p++) {
                int r = ks + (lane & 15);
                int c = warp_n * 32 + p * 16 + ((lane >> 4) << 3);
                u32 addr = b_smem + (u32)(r * 136 + c) * 2u;
                asm volatile(
                    "ldmatrix.sync.aligned.m8n8.x4.trans.shared.b16 {%0,%1,%2,%3}, [%4];"
                    : "=r"(bf[2*p][0]), "=r"(bf[2*p][1]),
                      "=r"(bf[2*p+1][0]), "=r"(bf[2*p+1][1])
                    : "r"(addr));
            }
            #pragma unroll
            for (int mi = 0; mi < 4; mi++)
                #pragma unroll
                for (int ni = 0; ni < 4; ni++) {
                    MMA16816(acc[mi][ni][0], acc[mi][ni][1],
                             acc[mi][ni][2], acc[mi][ni][3],
                             af[mi][0], af[mi][1], af[mi][2], af[mi][3],
                             bf[ni][0], bf[ni][1]);
                }
        }
        __syncthreads();
    }

    const int g = lane >> 2;
    const int t = lane & 3;

    if (ACT == 2) {
        #pragma unroll
        for (int mi = 0; mi < 4; mi++) {
            #pragma unroll
            for (int ni = 0; ni < 4; ni++) {
                const int c = warp_n * 32 + ni * 8 + (t << 1);
                float2 bb = *reinterpret_cast<const float2*>(&bias[c]);
                acc[mi][ni][0] += bb.x; acc[mi][ni][1] += bb.y;
                acc[mi][ni][2] += bb.x; acc[mi][ni][3] += bb.y;
            }
            float s0 = 0.f, q0 = 0.f, s1 = 0.f, q1 = 0.f;
            #pragma unroll
            for (int ni = 0; ni < 4; ni++) {
                s0 += acc[mi][ni][0] + acc[mi][ni][1];
                q0 += acc[mi][ni][0]*acc[mi][ni][0] + acc[mi][ni][1]*acc[mi][ni][1];
                s1 += acc[mi][ni][2] + acc[mi][ni][3];
                q1 += acc[mi][ni][2]*acc[mi][ni][2] + acc[mi][ni][3]*acc[mi][ni][3];
            }
            s0 += __shfl_xor_sync(0xffffffffu, s0, 1);
            s0 += __shfl_xor_sync(0xffffffffu, s0, 2);
            q0 += __shfl_xor_sync(0xffffffffu, q0, 1);
            q0 += __shfl_xor_sync(0xffffffffu, q0, 2);
            s1 += __shfl_xor_sync(0xffffffffu, s1, 1);
            s1 += __shfl_xor_sync(0xffffffffu, s1, 2);
            q1 += __shfl_xor_sync(0xffffffffu, q1, 1);
            q1 += __shfl_xor_sync(0xffffffffu, q1, 2);
            if (t == 0) {
                const int rl = warp_m * 64 + mi * 16 + g;
                red[rl][warp_n]     = make_float2(s0, q0);
                red[rl + 8][warp_n] = make_float2(s1, q1);
            }
        }
        __syncthreads();

        #pragma unroll
        for (int mi = 0; mi < 4; mi++) {
            const int rl0 = warp_m * 64 + mi * 16 + g;
            const int rl1 = rl0 + 8;
            float2 p;
            float s0 = 0.f, q0 = 0.f, s1 = 0.f, q1 = 0.f;
            #pragma unroll
            for (int w = 0; w < 4; w++) {
                p = red[rl0][w]; s0 += p.x; q0 += p.y;
                p = red[rl1][w]; s1 += p.x; q1 += p.y;
            }
            const float mu0 = s0 * (1.f/128.f);
            const float mu1 = s1 * (1.f/128.f);
            const float rs0 = rsqrtf(q0 * (1.f/128.f) - mu0*mu0 + 1e-5f);
            const float rs1 = rsqrtf(q1 * (1.f/128.f) - mu1*mu1 + 1e-5f);

            const size_t gr0 = (size_t)(brow + rl0) * 128;
            const size_t gr1 = (size_t)(brow + rl1) * 128;
            #pragma unroll
            for (int ni = 0; ni < 4; ni++) {
                const int c = warp_n * 32 + ni * 8 + (t << 1);
                float2 wv = *reinterpret_cast<const float2*>(&lnw[c]);
                float2 bv = *reinterpret_cast<const float2*>(&lnb[c]);
                float2 r0v = *reinterpret_cast<const float2*>(&res[gr0 + c]);
                float2 r1v = *reinterpret_cast<const float2*>(&res[gr1 + c]);
                float2 o0, o1;
                o0.x = r0v.x + (acc[mi][ni][0] - mu0) * rs0 * wv.x + bv.x;
                o0.y = r0v.y + (acc[mi][ni][1] - mu0) * rs0 * wv.y + bv.y;
                o1.x = r1v.x + (acc[mi][ni][2] - mu1) * rs1 * wv.x + bv.x;
                o1.y = r1v.y + (acc[mi][ni][3] - mu1) * rs1 * wv.y + bv.y;
                *reinterpret_cast<float2*>(&Cf[gr0 + c]) = o0;
                *reinterpret_cast<float2*>(&Cf[gr1 + c]) = o1;
            }
        }
        return;
    }

    #pragma unroll
    for (int mi = 0; mi < 4; mi++) {
        #pragma unroll
        for (int ni = 0; ni < 4; ni++) {
            const int r0 = brow + warp_m * 64 + mi * 16 + g;
            const int c  = bcol + warp_n * 32 + ni * 8 + (t << 1);
            float2 bb = *reinterpret_cast<const float2*>(&bias[c]);
            float2 v0, v1;
            v0.x = acc[mi][ni][0] + bb.x; v0.y = acc[mi][ni][1] + bb.y;
            v1.x = acc[mi][ni][2] + bb.x; v1.y = acc[mi][ni][3] + bb.y;
            if (ACT == 1) {
                v0.x *= normcdff(v0.x); v0.y *= normcdff(v0.y);
                v1.x *= normcdff(v1.x); v1.y *= normcdff(v1.y);
            }
            if (C_HALF) {
                *reinterpret_cast<__half2*>(&Ch[(size_t)r0 * N + c]) =
                    __float22half2_rn(v0);
                *reinterpret_cast<__half2*>(&Ch[(size_t)(r0 + 8) * N + c]) =
                    __float22half2_rn(v1);
            } else {
                *reinterpret_cast<float2*>(&Cf[(size_t)r0 * N + c])       = v0;
                *reinterpret_cast<float2*>(&Cf[(size_t)(r0 + 8) * N + c]) = v1;
            }
        }
    }
}

// ---------------------------------------------------------------------------
// Shifted bias in mma C-fragment layout, fp32:
// stored = (b(i,j) - scale_hd) * log2e.
// ---------------------------------------------------------------------------
__global__ void biasf_kernel(const int* __restrict__ rpi,
                             const float* __restrict__ table,
                             const float* __restrict__ logit_scale,
                             float4* __restrict__ biasF)
{
    const int unit = blockIdx.x * 8 + (threadIdx.x >> 5);
    const int qb = unit >> 5;
    const int jt = unit & 31;
    const int hd = blockIdx.y;
    const int lane = threadIdx.x & 31;
    const int g = lane >> 2, t = lane & 3;
    const int i0 = qb * 16, j0 = jt * 8;

    const float shift = __expf(fminf(logit_scale[hd], 4.6051702f)) * LOG2E;

    float4 r;
    r.x = table[rpi[(i0 + g)     * NTOK + j0 + 2*t    ] * NH + hd] * LOG2E - shift;
    r.y = table[rpi[(i0 + g)     * NTOK + j0 + 2*t + 1] * NH + hd] * LOG2E - shift;
    r.z = table[rpi[(i0 + g + 8) * NTOK + j0 + 2*t    ] * NH + hd] * LOG2E - shift;
    r.w = table[rpi[(i0 + g + 8) * NTOK + j0 + 2*t + 1] * NH + hd] * LOG2E - shift;
    biasF[((size_t)(hd * 16 + qb) * 32 + jt) * 32 + lane] = r;
}

// ---------------------------------------------------------------------------
// Quad query-blocked tensor-core window attention. Each warp handles its 4
// query blocks inside ONE jp loop: K and V fragments loaded once per jp and
// shared across all 4 query blocks (processed as 2 sub-pairs to bound
// register liveness). exp in fp32; denominator via ones-MMA.
// smem: Kh [256][24] + Vt [16][264] = 20.4 KB.
// ---------------------------------------------------------------------------
#define SKH  0
#define SVTH (256*24)
#define ATTN_SMEM_HALFS (256*24 + 16*264)
#define ONE2 0x3C003C00u

__global__ __launch_bounds__(128, 4) void attn_tc_kernel(
    const __half* __restrict__ qkv, const float4* __restrict__ biasF,
    const float* __restrict__ logit_scale, __half* __restrict__ attn_out)
{
    __shared__ __half sm[ATTN_SMEM_HALFS];

    const int wi = blockIdx.x;
    const int hd = blockIdx.y;
    const int tid = threadIdx.x;

    const int bimg = wi / 144;
    const int wrem = wi % 144;
    const int wr = wrem / WPR, wc = wrem % WPR;
    const int rowbase = bimg * (IMG * IMG) + (wr * 16) * IMG + wc * 16;

    const float scale = __expf(fminf(logit_scale[hd], 4.6051702f));
    const float qmul  = scale * LOG2E;

    for (int tok = tid; tok < NTOK; tok += 128) {
        const int m = rowbase + (tok >> 4) * IMG + (tok & 15);
        const __half* base = qkv + (size_t)m * 384 + hd * HD;

        uint4 kraw0 = *reinterpret_cast<const uint4*>(base + 128);
        uint4 kraw1 = *reinterpret_cast<const uint4*>(base + 136);
        uint4 vraw0 = *reinterpret_cast<const uint4*>(base + 256);
        uint4 vraw1 = *reinterpret_cast<const uint4*>(base + 264);

        float kf[16];
        {
            const __half2* k2a = reinterpret_cast<const __half2*>(&kraw0);
            const __half2* k2b = reinterpret_cast<const __half2*>(&kraw1);
            #pragma unroll
            for (int z = 0; z < 4; z++) {
                float2 f = __half22float2(k2a[z]);
                kf[2*z] = f.x; kf[2*z+1] = f.y;
                f = __half22float2(k2b[z]);
                kf[8+2*z] = f.x; kf[8+2*z+1] = f.y;
            }
        }
        float ks = 0.f;
        #pragma unroll
        for (int z = 0; z < 16; z++) ks += kf[z] * kf[z];
        const float kr = 1.f / fmaxf(sqrtf(ks), 1e-12f);
        #pragma unroll
        for (int z = 0; z < 16; z++)
            sm[SKH + tok*24 + z] = __float2half_rn(kf[z] * kr);

        const __half* vh = reinterpret_cast<const __half*>(&vraw0);
        #pragma unroll
        for (int z = 0; z < 8; z++) sm[SVTH + z*264 + tok] = vh[z];
        vh = reinterpret_cast<const __half*>(&vraw1);
        #pragma unroll
        for (int z = 0; z < 8; z++) sm[SVTH + (8+z)*264 + tok] = vh[z];
    }
    __syncthreads();

    const int warp = tid >> 5;
    const int lane = tid & 31;
    const int g = lane >> 2;
    const int t = lane & 3;

    // ---- load + normalize q for all 4 query blocks of this warp
    int mloc[4][2];
    u32 qa[4][4];
    #pragma unroll
    for (int q4 = 0; q4 < 4; q4++) {
        const int qb = warp * 4 + q4;
        const int i0 = qb * 16;
        const int r0 = i0 + g, r1 = i0 + g + 8;
        const int m0 = rowbase + (r0 >> 4) * IMG + (r0 & 15);
        const int m1 = rowbase + (r1 >> 4) * IMG + (r1 & 15);
        mloc[q4][0] = m0; mloc[q4][1] = m1;

        const __half* p0 = qkv + (size_t)m0 * 384 + hd * HD;
        const __half* p1 = qkv + (size_t)m1 * 384 + hd * HD;
        float2 a00 = __half22float2(*reinterpret_cast<const __half2*>(p0 + 2*t));
        float2 a01 = __half22float2(*reinterpret_cast<const __half2*>(p0 + 2*t + 8));
        float2 a10 = __half22float2(*reinterpret_cast<const __half2*>(p1 + 2*t));
        float2 a11 = __half22float2(*reinterpret_cast<const __half2*>(p1 + 2*t + 8));

        float s0 = a00.x*a00.x + a00.y*a00.y + a01.x*a01.x + a01.y*a01.y;
        float s1 = a10.x*a10.x + a10.y*a10.y + a11.x*a11.x + a11.y*a11.y;
        s0 += __shfl_xor_sync(0xffffffffu, s0, 1);
        s0 += __shfl_xor_sync(0xffffffffu, s0, 2);
        s1 += __shfl_xor_sync(0xffffffffu, s1, 1);
        s1 += __shfl_xor_sync(0xffffffffu, s1, 2);
        const float qr0 = qmul / fmaxf(sqrtf(s0), 1e-12f);
        const float qr1 = qmul / fmaxf(sqrtf(s1), 1e-12f);

        __half2 h;
        h = __floats2half2_rn(a00.x * qr0, a00.y * qr0); qa[q4][0] = *reinterpret_cast<u32*>(&h);
        h = __floats2half2_rn(a10.x * qr1, a10.y * qr1); qa[q4][1] = *reinterpret_cast<u32*>(&h);
        h = __floats2half2_rn(a01.x * qr0, a01.y * qr0); qa[q4][2] = *reinterpret_cast<u32*>(&h);
        h = __floats2half2_rn(a11.x * qr1, a11.y * qr1); qa[q4][3] = *reinterpret_cast<u32*>(&h);
    }

    float o[4][8];
    float l[4][4];
    #pragma unroll
    for (int q4 = 0; q4 < 4; q4++) {
        #pragma unroll
        for (int z = 0; z < 8; z++) o[q4][z] = 0.f;
        #pragma unroll
        for (int z = 0; z < 4; z++) l[q4][z] = 0.f;
    }

    const float4* bp0 = biasF + ((size_t)(hd * 16 + warp * 4) * 32) * 32 + lane;
    const int QSTRIDE = 32 * 32;   // one qb of bias fragments

    #pragma unroll 2
    for (int jp = 0; jp < 16; jp++) {
        const int j0a = (2 * jp) * 8;
        const int j0b = (2 * jp + 1) * 8;

        // shared K fragments
        u32 kh0 = *reinterpret_cast<u32*>(&sm[SKH + (j0a+g)*24 + 2*t]);
        u32 kh1 = *reinterpret_cast<u32*>(&sm[SKH + (j0a+g)*24 + 2*t + 8]);
        u32 mh0 = *reinterpret_cast<u32*>(&sm[SKH + (j0b+g)*24 + 2*t]);
        u32 mh1 = *reinterpret_cast<u32*>(&sm[SKH + (j0b+g)*24 + 2*t + 8]);
        // shared V fragments
        const int jb = jp * 16;
        u32 vh0 = *reinterpret_cast<u32*>(&sm[SVTH + g*264 + jb + 2*t]);
        u32 vh1 = *reinterpret_cast<u32*>(&sm[SVTH + g*264 + jb + 2*t + 8]);
        u32 wh0 = *reinterpret_cast<u32*>(&sm[SVTH + (8+g)*264 + jb + 2*t]);
        u32 wh1 = *reinterpret_cast<u32*>(&sm[SVTH + (8+g)*264 + jb + 2*t + 8]);

        #pragma unroll
        for (int sp = 0; sp < 2; sp++) {
            const int qx = sp * 2, qy = sp * 2 + 1;
            float4 bx0 = __ldg(&bp0[(size_t)qx * QSTRIDE + (2 * jp) * 32]);
            float4 bx1 = __ldg(&bp0[(size_t)qx * QSTRIDE + (2 * jp + 1) * 32]);
            float4 by0 = __ldg(&bp0[(size_t)qy * QSTRIDE + (2 * jp) * 32]);
            float4 by1 = __ldg(&bp0[(size_t)qy * QSTRIDE + (2 * jp + 1) * 32]);

            float sXa0=0,sXa1=0,sXa2=0,sXa3=0, sXb0=0,sXb1=0,sXb2=0,sXb3=0;
            MMA16816(sXa0,sXa1,sXa2,sXa3, qa[qx][0],qa[qx][1],qa[qx][2],qa[qx][3], kh0,kh1);
            MMA16816(sXb0,sXb1,sXb2,sXb3, qa[qx][0],qa[qx][1],qa[qx][2],qa[qx][3], mh0,mh1);
            float sYa0=0,sYa1=0,sYa2=0,sYa3=0, sYb0=0,sYb1=0,sYb2=0,sYb3=0;
            MMA16816(sYa0,sYa1,sYa2,sYa3, qa[qy][0],qa[qy][1],qa[qy][2],qa[qy][3], kh0,kh1);
            MMA16816(sYb0,sYb1,sYb2,sYb3, qa[qy][0],qa[qy][1],qa[qy][2],qa[qy][3], mh0,mh1);

            // fp32 exp2 on shifted logits, then pack p -> fp16 fragments
            __half2 h;
            h = __floats2half2_rn(ex2f(sXa0 + bx0.x), ex2f(sXa1 + bx0.y));
            u32 aX0 = *reinterpret_cast<u32*>(&h);
            h = __floats2half2_rn(ex2f(sXa2 + bx0.z), ex2f(sXa3 + bx0.w));
            u32 aX1 = *reinterpret_cast<u32*>(&h);
            h = __floats2half2_rn(ex2f(sXb0 + bx1.x), ex2f(sXb1 + bx1.y));
            u32 aX2 = *reinterpret_cast<u32*>(&h);
            h = __floats2half2_rn(ex2f(sXb2 + bx1.z), ex2f(sXb3 + bx1.w));
            u32 aX3 = *reinterpret_cast<u32*>(&h);
            h = __floats2half2_rn(ex2f(sYa0 + by0.x), ex2f(sYa1 + by0.y));
            u32 aY0 = *reinterpret_cast<u32*>(&h);
            h = __floats2half2_rn(ex2f(sYa2 + by0.z), ex2f(sYa3 + by0.w));
            u32 aY1 = *reinterpret_cast<u32*>(&h);
            h = __floats2half2_rn(ex2f(sYb0 + by1.x), ex2f(sYb1 + by1.y));
            u32 aY2 = *reinterpret_cast<u32*>(&h);
            h = __floats2half2_rn(ex2f(sYb2 + by1.z), ex2f(sYb3 + by1.w));
            u32 aY3 = *reinterpret_cast<u32*>(&h);

            MMA16816(o[qx][0],o[qx][1],o[qx][2],o[qx][3], aX0,aX1,aX2,aX3, vh0,vh1);
            MMA16816(o[qx][4],o[qx][5],o[qx][6],o[qx][7], aX0,aX1,aX2,aX3, wh0,wh1);
            MMA16816(l[qx][0],l[qx][1],l[qx][2],l[qx][3], aX0,aX1,aX2,aX3, ONE2,ONE2);
            MMA16816(o[qy][0],o[qy][1],o[qy][2],o[qy][3], aY0,aY1,aY2,aY3, vh0,vh1);
            MMA16816(o[qy][4],o[qy][5],o[qy][6],o[qy][7], aY0,aY1,aY2,aY3, wh0,wh1);
            MMA16816(l[qy][0],l[qy][1],l[qy][2],l[qy][3], aY0,aY1,aY2,aY3, ONE2,ONE2);
        }
    }

    const int col = hd * HD + 2 * t;
    #pragma unroll
    for (int q4 = 0; q4 < 4; q4++) {
        const float i0 = 1.f / l[q4][0];
        const float i1 = 1.f / l[q4][2];
        const int m0 = mloc[q4][0], m1 = mloc[q4][1];
        *reinterpret_cast<__half2*>(&attn_out[(size_t)m0 * C_DIM + col]) =
            __floats2half2_rn(o[q4][0] * i0, o[q4][1] * i0);
        *reinterpret_cast<__half2*>(&attn_out[(size_t)m1 * C_DIM + col]) =
            __floats2half2_rn(o[q4][2] * i1, o[q4][3] * i1);
        *reinterpret_cast<__half2*>(&attn_out[(size_t)m0 * C_DIM + col + 8]) =
            __floats2half2_rn(o[q4][4] * i0, o[q4][5] * i0);
        *reinterpret_cast<__half2*>(&attn_out[(size_t)m1 * C_DIM + col + 8]) =
            __floats2half2_rn(o[q4][6] * i1, o[q4][7] * i1);
    }
}

// ---------------------------------------------------------------------------
extern "C" void kernel_launch(void* const* d_in, const int* in_sizes, int n_in,
                              void* d_out, int out_size)
{
    const float* x           = (const float*)d_in[0];
    const float* qkv_w       = (const float*)d_in[1];
    const float* qkv_b       = (const float*)d_in[2];
    const float* proj_w      = (const float*)d_in[3];
    const float* proj_b      = (const float*)d_in[4];
    const float* logit_scale = (const float*)d_in[5];
    const float* rpb_table   = (const float*)d_in[6];
    const float* n1w         = (const float*)d_in[7];
    const float* n1b         = (const float*)d_in[8];
    const float* n2w         = (const float*)d_in[9];
    const float* n2b         = (const float*)d_in[10];
    const float* fc1_w       = (const float*)d_in[11];
    const float* fc1_b       = (const float*)d_in[12];
    const float* fc2_w       = (const float*)d_in[13];
    const float* fc2_b       = (const float*)d_in[14];
    const int*   rpi         = (const int*)d_in[17];
    float* out = (float*)d_out;

    float *p_x1;
    __half *p_qkvh, *p_attnh, *p_hidh;
    float4 *p_biasF;
    cudaGetSymbolAddress((void**)&p_qkvh,  g_qkvh);
    cudaGetSymbolAddress((void**)&p_biasF, g_biasF);
    cudaGetSymbolAddress((void**)&p_attnh, g_attnh);
    cudaGetSymbolAddress((void**)&p_x1,    g_x1);
    cudaGetSymbolAddress((void**)&p_hidh,  g_hidh);

    // 1) shifted bias fragments (fp32)
    biasf_kernel<<<dim3(64, NH), 256>>>(rpi, rpb_table, logit_scale, p_biasF);

    // 2) QKV: fp32 A, fp16 C
    hgemm_kernel<false,true,0><<<dim3(384/128, M_TOK/128), 256>>>(
        x, qkv_w, qkv_b, p_qkvh, M_TOK, 384, 128, nullptr, nullptr, nullptr);

    // 3) quad query-blocked attention (fp32 exp, MMA row sums)
    attn_tc_kernel<<<dim3(NWIN, NH), 128>>>(p_qkvh, p_biasF, logit_scale, p_attnh);

    // 4) proj + fused LN + residual
    hgemm_kernel<true,false,2><<<dim3(1, M_TOK/128), 256>>>(
        p_attnh, proj_w, proj_b, p_x1, M_TOK, 128, 128, x, n1w, n1b);

    // 5) fc1 + GELU
    hgemm_kernel<false,true,1><<<dim3(256/128, M_TOK/128), 256>>>(
        p_x1, fc1_w, fc1_b, p_hidh, M_TOK, 256, 128, nullptr, nullptr, nullptr);

    // 6) fc2 + fused LN + residual
    hgemm_kernel<true,false,2><<<dim3(1, M_TOK/128), 256>>>(
        p_hidh, fc2_w, fc2_b, out, M_TOK, 128, 256, p_x1, n2w, n2b);
}